// round 15
// baseline (speedup 1.0000x reference)
#include <cuda_runtime.h>
#include <cuda_bf16.h>
#include <mma.h>
#include <math.h>

// GRU: B=128, T=512, I=256, H=512. out = final h [1,128,512] fp32.
// Persistent kernel, 128 CTAs (4 batch x 32 j), wmma bf16 hi/lo 3-product.
// R14 structure with x-stage(t+1) folded into the gate phase: 4 syncs/step,
// x DRAM latency hidden under gate math, chunk0 starts immediately at step
// head to overlap the inter-CTA flag wait. Flag sync, register h_old.

using namespace nvcuda;

#define BATCH 128
#define TT    512
#define II    256
#define HH    512
#define GB    4
#define GJ    32
#define BC    32
#define JC    16
#define NCTA  128
#define NSYNC 32
#define NTHR  512

#define WSTRIDE 776     // u16 per fused W row (768+8)
#define USTRIDE 264     // u16 per U row (256+8)

// SMEM byte offsets
#define SM_WH   0
#define SM_WL   (SM_WH  + 48*WSTRIDE*2)
#define SM_UH1  (SM_WL  + 48*WSTRIDE*2)        // buf1 = h[0:256]
#define SM_UL1  (SM_UH1 + 32*USTRIDE*2)
#define SM_UH0  (SM_UL1 + 32*USTRIDE*2)        // buf0 = x / h[256:512]
#define SM_UL0  (SM_UH0 + 32*USTRIDE*2)
#define SM_DRED (SM_UL0 + 32*USTRIDE*2)        // 12 tiles * 256 f32
#define SM_DXN  (SM_DRED + 12*256*4)           // 2 tiles * 256 f32
#define SM_BS   (SM_DXN + 2*256*4)             // 64 f32
#define SMEM_BYTES (SM_BS + 256)               // 231168

__device__ unsigned short g_hsh[2][BATCH*HH];
__device__ unsigned short g_hsl[2][BATCH*HH];
__device__ unsigned short g_xh [(size_t)BATCH*TT*II];
__device__ unsigned short g_xl [(size_t)BATCH*TT*II];
__device__ __align__(128) unsigned int g_flags[GB][32];
__device__ unsigned int   g_count = 0;
__device__ unsigned int   g_phase = 0;

__device__ __forceinline__ float sigm(float x) {
    return 1.0f / (1.0f + __expf(-x));
}
__device__ __forceinline__ unsigned short bhi(float v) {
    return __bfloat16_as_ushort(__float2bfloat16(v));
}
__device__ __forceinline__ unsigned short blo(float v) {
    __nv_bfloat16 h = __float2bfloat16(v);
    return __bfloat16_as_ushort(__float2bfloat16(v - __bfloat162float(h)));
}

extern "C" __global__ void __launch_bounds__(NTHR, 1)
gru_persistent_kernel(const float* __restrict__ x,      // [B, T, I]
                      const float* __restrict__ W_ih,   // [3H, I]
                      const float* __restrict__ W_hh,   // [3H, H]
                      const float* __restrict__ b_ih,   // [3H]
                      const float* __restrict__ b_hh,   // [3H]
                      float* __restrict__ out)          // [1, B, H]
{
    extern __shared__ char smem[];
    unsigned short* Wh  = (unsigned short*)(smem + SM_WH);
    unsigned short* Wl  = (unsigned short*)(smem + SM_WL);
    unsigned short* Uh1 = (unsigned short*)(smem + SM_UH1);
    unsigned short* Ul1 = (unsigned short*)(smem + SM_UL1);
    unsigned short* Uh0 = (unsigned short*)(smem + SM_UH0);
    unsigned short* Ul0 = (unsigned short*)(smem + SM_UL0);
    float* Dred = (float*)(smem + SM_DRED);
    float* Dxn  = (float*)(smem + SM_DXN);
    float* B_s  = (float*)(smem + SM_BS);

    const int tid = threadIdx.x;
    const int bx  = blockIdx.x;
    const int gb  = bx & (GB - 1);
    const int gj  = bx >> 2;
    const int b0  = gb * BC;
    const int j0  = gj * JC;

    // relative-phase base for the (self-cleaning) init barrier
    unsigned base = 0;
    if (tid == 0) base = *((volatile unsigned*)&g_phase);

    // ---- one-time: fused W tile hi/lo (rows 0-15 r, 16-31 z, 32-47 n) ----
    for (int idx = tid; idx < 48 * 768; idx += NTHR) {
        int row = idx / 768;
        int col = idx - row * 768;
        int G = (row < 16) ? j0 + row
              : (row < 32) ? 512 + j0 + (row - 16)
                           : 1024 + j0 + (row - 32);
        float v = (col < II) ? W_ih[G * II + col] : W_hh[G * HH + (col - II)];
        Wh[row * WSTRIDE + col] = bhi(v);
        Wl[row * WSTRIDE + col] = blo(v);
    }
    if (tid < 64) {
        int i = tid & 15;
        float v;
        if (tid < 16)      v = b_ih[j0 + i]       + b_hh[j0 + i];        // r
        else if (tid < 32) v = b_ih[512 + j0 + i] + b_hh[512 + j0 + i];  // z
        else if (tid < 48) v = b_ih[1024 + j0 + i];                      // xn
        else               v = b_hh[1024 + j0 + i];                      // hn
        B_s[tid] = v;
    }

    // ---- pre-phase: split x into hi/lo planes; zero own h0 tile; flags ----
    {
        const size_t total = (size_t)BATCH * TT * II;
        for (size_t i = (size_t)(bx * NTHR + tid) * 8; i < total;
             i += (size_t)NCTA * NTHR * 8) {
            float4 v0 = *(const float4*)(x + i);
            float4 v1 = *(const float4*)(x + i + 4);
            float vv[8] = {v0.x, v0.y, v0.z, v0.w, v1.x, v1.y, v1.z, v1.w};
            unsigned hs[8], ls[8];
            #pragma unroll
            for (int j = 0; j < 8; j++) {
                hs[j] = bhi(vv[j]);
                ls[j] = blo(vv[j]);
            }
            uint4 ph, pl;
            ph.x = hs[0] | (hs[1] << 16); ph.y = hs[2] | (hs[3] << 16);
            ph.z = hs[4] | (hs[5] << 16); ph.w = hs[6] | (hs[7] << 16);
            pl.x = ls[0] | (ls[1] << 16); pl.y = ls[2] | (ls[3] << 16);
            pl.z = ls[4] | (ls[5] << 16); pl.w = ls[6] | (ls[7] << 16);
            *(uint4*)(g_xh + i) = ph;
            *(uint4*)(g_xl + i) = pl;
        }
        for (int i = tid; i < BC * JC; i += NTHR) {
            int b = i >> 4, j = i & 15;
            int gi = (b0 + b) * HH + j0 + j;
            g_hsh[0][gi] = 0;
            g_hsl[0][gi] = 0;
        }
        if (tid == 0) *((volatile unsigned*)&g_flags[gb][gj]) = 0u;
    }

    // init barrier (global, count-based, self-cleaning)
    __syncthreads();
    if (tid == 0) {
        __threadfence();
        if (atomicAdd(&g_count, 1u) == NCTA - 1u) {
            g_count = 0;
            __threadfence();
            *((volatile unsigned*)&g_phase) = base + 1u;
        }
        while ((unsigned)(*((volatile unsigned*)&g_phase) - base) < 1u) {
            __nanosleep(32);
        }
        __threadfence();
    }
    __syncthreads();

    // mma warp roles: w<12 -> (btile, ntile, kh)
    const int w     = tid >> 5;
    const int lane  = tid & 31;
    const int kh    = w & 1;
    const int tau   = w >> 1;
    const int btile = tau / 3;
    const int ntile = tau % 3;

    wmma::fragment<wmma::matrix_a, 16, 16, 16, __nv_bfloat16, wmma::row_major> fa_h, fa_l;
    wmma::fragment<wmma::matrix_b, 16, 16, 16, __nv_bfloat16, wmma::col_major> fb_h, fb_l;
    wmma::fragment<wmma::accumulator, 16, 16, 16, float> facc;

    // staging indices
    const int srow = tid >> 4;          // 0..31
    const int sk16 = (tid & 15) * 16;
    const int sk32 = (tid & 15) * 32;

    // gate-phase mapping (one (b, j) element per thread)
    const int jj  = tid & 15;
    const int bb  = tid >> 4;           // 0..31
    const int gbt = bb >> 4;
    const float bias_r  = B_s[jj];
    const float bias_z  = B_s[16 + jj];
    const float bias_xn = B_s[32 + jj];
    const float bias_hn = B_s[48 + jj];
    const int loc = (bb & 15) * 16 + jj;
    float hold = 0.0f;

    // x-stage helper: copy packed x(t) planes into buf0
    auto stage_x = [&](int t) {
        const size_t off = ((size_t)(b0 + srow) * TT + t) * II + sk16;
        const uint4* sh = (const uint4*)(g_xh + off);
        const uint4* sl = (const uint4*)(g_xl + off);
        uint4* dh = (uint4*)(Uh0 + srow * USTRIDE + sk16);
        uint4* dl = (uint4*)(Ul0 + srow * USTRIDE + sk16);
        dh[0] = sh[0]; dh[1] = sh[1];
        dl[0] = sl[0]; dl[1] = sl[1];
    };

    // prologue: stage x(0)
    stage_x(0);
    __syncthreads();

    for (int t = 0; t < TT; t++) {
        const int rp = t & 1;
        const int wp = rp ^ 1;

        // ---- chunk 0: x projection from buf0 (staged last iteration) ----
        if (w < 12) {
            wmma::fill_fragment(facc, 0.0f);
            const __nv_bfloat16* Ah = (const __nv_bfloat16*)(Uh0 + btile * 16 * USTRIDE);
            const __nv_bfloat16* Al = (const __nv_bfloat16*)(Ul0 + btile * 16 * USTRIDE);
            const __nv_bfloat16* Bh = (const __nv_bfloat16*)(Wh + ntile * 16 * WSTRIDE);
            const __nv_bfloat16* Bl = (const __nv_bfloat16*)(Wl + ntile * 16 * WSTRIDE);
            if (ntile < 2) {
                #pragma unroll
                for (int ks = kh * 8; ks < kh * 8 + 8; ks++) {
                    wmma::load_matrix_sync(fa_h, Ah + ks * 16, USTRIDE);
                    wmma::load_matrix_sync(fa_l, Al + ks * 16, USTRIDE);
                    wmma::load_matrix_sync(fb_h, Bh + ks * 16, WSTRIDE);
                    wmma::load_matrix_sync(fb_l, Bl + ks * 16, WSTRIDE);
                    wmma::mma_sync(facc, fa_h, fb_h, facc);
                    wmma::mma_sync(facc, fa_h, fb_l, facc);
                    wmma::mma_sync(facc, fa_l, fb_h, facc);
                }
            } else if (kh == 0) {   // ntile==2: one warp does all 16 ks, stores xn
                #pragma unroll
                for (int ks = 0; ks < 16; ks++) {
                    wmma::load_matrix_sync(fa_h, Ah + ks * 16, USTRIDE);
                    wmma::load_matrix_sync(fa_l, Al + ks * 16, USTRIDE);
                    wmma::load_matrix_sync(fb_h, Bh + ks * 16, WSTRIDE);
                    wmma::load_matrix_sync(fb_l, Bl + ks * 16, WSTRIDE);
                    wmma::mma_sync(facc, fa_h, fb_h, facc);
                    wmma::mma_sync(facc, fa_h, fb_l, facc);
                    wmma::mma_sync(facc, fa_l, fb_h, facc);
                }
                wmma::store_matrix_sync(Dxn + btile * 256, facc, 16, wmma::mem_row_major);
                wmma::fill_fragment(facc, 0.0f);
            }
        }

        // ---- wait: 32 producer flags >= t (warp 0 parallel poll) ----
        if (w == 0) {
            const volatile unsigned* fl = &g_flags[gb][0];
            for (;;) {
                unsigned v = fl[lane];
                if (!__any_sync(0xFFFFFFFFu, v < (unsigned)t)) break;
                __nanosleep(32);
            }
            __threadfence();
        }
        __syncthreads();

        // ---- stage h planes: h[0:256]->buf1, h[256:512]->buf0 ----
        {
            const int goff = (b0 + srow) * HH + sk32;
            const uint4* sh = (const uint4*)(g_hsh[rp] + goff);
            const uint4* sl = (const uint4*)(g_hsl[rp] + goff);
            uint4 *dh, *dl;
            if (sk32 < 256) {
                dh = (uint4*)(Uh1 + srow * USTRIDE + sk32);
                dl = (uint4*)(Ul1 + srow * USTRIDE + sk32);
            } else {
                dh = (uint4*)(Uh0 + srow * USTRIDE + (sk32 - 256));
                dl = (uint4*)(Ul0 + srow * USTRIDE + (sk32 - 256));
            }
            dh[0] = sh[0]; dh[1] = sh[1]; dh[2] = sh[2]; dh[3] = sh[3];
            dl[0] = sl[0]; dl[1] = sl[1]; dl[2] = sl[2]; dl[3] = sl[3];
        }
        __syncthreads();

        // ---- chunks 1 (buf1) + 2 (buf0): h projection ----
        if (w < 12) {
            #pragma unroll
            for (int c = 1; c < 3; c++) {
                const unsigned short* UhB = (c == 1) ? Uh1 : Uh0;
                const unsigned short* UlB = (c == 1) ? Ul1 : Ul0;
                const __nv_bfloat16* Ah = (const __nv_bfloat16*)(UhB + btile * 16 * USTRIDE);
                const __nv_bfloat16* Al = (const __nv_bfloat16*)(UlB + btile * 16 * USTRIDE);
                const __nv_bfloat16* Bh = (const __nv_bfloat16*)(Wh + ntile * 16 * WSTRIDE + c * 256);
                const __nv_bfloat16* Bl = (const __nv_bfloat16*)(Wl + ntile * 16 * WSTRIDE + c * 256);
                #pragma unroll
                for (int ks = kh * 8; ks < kh * 8 + 8; ks++) {
                    wmma::load_matrix_sync(fa_h, Ah + ks * 16, USTRIDE);
                    wmma::load_matrix_sync(fa_l, Al + ks * 16, USTRIDE);
                    wmma::load_matrix_sync(fb_h, Bh + ks * 16, WSTRIDE);
                    wmma::load_matrix_sync(fb_l, Bl + ks * 16, WSTRIDE);
                    wmma::mma_sync(facc, fa_h, fb_h, facc);
                    wmma::mma_sync(facc, fa_h, fb_l, facc);
                    wmma::mma_sync(facc, fa_l, fb_h, facc);
                }
            }
            wmma::store_matrix_sync(Dred + ((btile * 3 + ntile) * 2 + kh) * 256,
                                    facc, 16, wmma::mem_row_major);
        }
        __syncthreads();

        // ---- gates + h update + x-stage(t+1) (hidden under gate math) ----
        {
            float dr  = Dred[((gbt * 3 + 0) * 2 + 0) * 256 + loc]
                      + Dred[((gbt * 3 + 0) * 2 + 1) * 256 + loc];
            float dz  = Dred[((gbt * 3 + 1) * 2 + 0) * 256 + loc]
                      + Dred[((gbt * 3 + 1) * 2 + 1) * 256 + loc];
            float dhn = Dred[((gbt * 3 + 2) * 2 + 0) * 256 + loc]
                      + Dred[((gbt * 3 + 2) * 2 + 1) * 256 + loc];
            float dxn = Dxn[gbt * 256 + loc];

            if (t + 1 < TT) stage_x(t + 1);   // buf0 dead: mma12 done reading

            float r = sigm(dr + bias_r);
            float z = sigm(dz + bias_z);
            float n = tanhf(dxn + bias_xn + r * (dhn + bias_hn));
            hold = n + z * (hold - n);
            const int gi = (b0 + bb) * HH + j0 + jj;
            g_hsh[wp][gi] = bhi(hold);
            g_hsl[wp][gi] = blo(hold);
            if (t == TT - 1) out[gi] = hold;
        }
        __syncthreads();

        // ---- publish: flag = t+1 ----
        if (tid == 0) {
            __threadfence();
            *((volatile unsigned*)&g_flags[gb][gj]) = (unsigned)(t + 1);
        }
    }
}

extern "C" void kernel_launch(void* const* d_in, const int* in_sizes, int n_in,
                              void* d_out, int out_size) {
    (void)in_sizes; (void)n_in; (void)out_size;
    cudaFuncSetAttribute(gru_persistent_kernel,
                         cudaFuncAttributeMaxDynamicSharedMemorySize, SMEM_BYTES);
    gru_persistent_kernel<<<NCTA, NTHR, SMEM_BYTES>>>(
        (const float*)d_in[0],
        (const float*)d_in[1],
        (const float*)d_in[2],
        (const float*)d_in[3],
        (const float*)d_in[4],
        (float*)d_out);
}

// round 16
// speedup vs baseline: 1.4596x; 1.4596x over previous
#include <cuda_runtime.h>
#include <cuda_bf16.h>
#include <mma.h>
#include <math.h>

// GRU: B=128, T=512, I=256, H=512. out = final h [1,128,512] fp32.
// Persistent kernel, 128 CTAs (4 batch x 32 j), wmma bf16 hi/lo 3-product.
// PING-PONG over batch halves (16 rows each): two mini-steps per t with
// independent producer flags; one half's inter-CTA wait hides under the
// other half's compute. x-stage of the next half runs in the gate phase on
// the idle thread half, strictly after that half's own flag publish.

using namespace nvcuda;

#define BATCH 128
#define TT    512
#define II    256
#define HH    512
#define GB    4
#define GJ    32
#define BC    32
#define JC    16
#define NCTA  128
#define NTHR  512

#define WSTRIDE 776     // u16 per fused W row (768+8)
#define USTRIDE 264     // u16 per U row (256+8)

// SMEM byte offsets (16-row half buffers)
#define SM_WH   0                         // 48*776*2 = 74496
#define SM_WL   74496                     // -> 148992
#define SM_BH1H 148992                    // h[0:256] hi   16*264*2 = 8448
#define SM_BH1L 157440                    // h[0:256] lo
#define SM_BUH  165888                    // x / h[256:512] hi
#define SM_BUL  174336                    // x / h[256:512] lo
#define SM_DRED 182784                    // 12 tiles * 1024 = 12288
#define SM_DXN  195072                    // 4 tiles * 1024 = 4096
#define SM_BS   199168                    // 64 f32
#define SMEM_BYTES 199680

__device__ unsigned short g_hsh[2][BATCH*HH];
__device__ unsigned short g_hsl[2][BATCH*HH];
__device__ unsigned short g_xh [(size_t)BATCH*TT*II];
__device__ unsigned short g_xl [(size_t)BATCH*TT*II];
__device__ __align__(128) unsigned int g_flags[GB*2][32];  // per (gb, half)
__device__ unsigned int   g_count = 0;
__device__ unsigned int   g_phase = 0;

__device__ __forceinline__ float sigm(float x) {
    return 1.0f / (1.0f + __expf(-x));
}
__device__ __forceinline__ unsigned short bhi(float v) {
    return __bfloat16_as_ushort(__float2bfloat16(v));
}
__device__ __forceinline__ unsigned short blo(float v) {
    __nv_bfloat16 h = __float2bfloat16(v);
    return __bfloat16_as_ushort(__float2bfloat16(v - __bfloat162float(h)));
}

extern "C" __global__ void __launch_bounds__(NTHR, 1)
gru_persistent_kernel(const float* __restrict__ x,      // [B, T, I]
                      const float* __restrict__ W_ih,   // [3H, I]
                      const float* __restrict__ W_hh,   // [3H, H]
                      const float* __restrict__ b_ih,   // [3H]
                      const float* __restrict__ b_hh,   // [3H]
                      float* __restrict__ out)          // [1, B, H]
{
    extern __shared__ char smem[];
    unsigned short* Wh   = (unsigned short*)(smem + SM_WH);
    unsigned short* Wl   = (unsigned short*)(smem + SM_WL);
    unsigned short* BH1h = (unsigned short*)(smem + SM_BH1H);
    unsigned short* BH1l = (unsigned short*)(smem + SM_BH1L);
    unsigned short* BUh  = (unsigned short*)(smem + SM_BUH);
    unsigned short* BUl  = (unsigned short*)(smem + SM_BUL);
    float* Dred = (float*)(smem + SM_DRED);
    float* Dxn  = (float*)(smem + SM_DXN);
    float* B_s  = (float*)(smem + SM_BS);

    const int tid = threadIdx.x;
    const int bx  = blockIdx.x;
    const int gb  = bx & (GB - 1);
    const int gj  = bx >> 2;
    const int b0  = gb * BC;
    const int j0  = gj * JC;

    unsigned base = 0;
    if (tid == 0) base = *((volatile unsigned*)&g_phase);

    // ---- one-time: fused W tile hi/lo (rows 0-15 r, 16-31 z, 32-47 n) ----
    for (int idx = tid; idx < 48 * 768; idx += NTHR) {
        int row = idx / 768;
        int col = idx - row * 768;
        int G = (row < 16) ? j0 + row
              : (row < 32) ? 512 + j0 + (row - 16)
                           : 1024 + j0 + (row - 32);
        float v = (col < II) ? W_ih[G * II + col] : W_hh[G * HH + (col - II)];
        Wh[row * WSTRIDE + col] = bhi(v);
        Wl[row * WSTRIDE + col] = blo(v);
    }
    if (tid < 64) {
        int i = tid & 15;
        float v;
        if (tid < 16)      v = b_ih[j0 + i]       + b_hh[j0 + i];        // r
        else if (tid < 32) v = b_ih[512 + j0 + i] + b_hh[512 + j0 + i];  // z
        else if (tid < 48) v = b_ih[1024 + j0 + i];                      // xn
        else               v = b_hh[1024 + j0 + i];                      // hn
        B_s[tid] = v;
    }

    // ---- pre-phase: split x into hi/lo planes; zero own h0 tile; flags ----
    {
        const size_t total = (size_t)BATCH * TT * II;
        for (size_t i = (size_t)(bx * NTHR + tid) * 8; i < total;
             i += (size_t)NCTA * NTHR * 8) {
            float4 v0 = *(const float4*)(x + i);
            float4 v1 = *(const float4*)(x + i + 4);
            float vv[8] = {v0.x, v0.y, v0.z, v0.w, v1.x, v1.y, v1.z, v1.w};
            unsigned hs[8], ls[8];
            #pragma unroll
            for (int j = 0; j < 8; j++) {
                hs[j] = bhi(vv[j]);
                ls[j] = blo(vv[j]);
            }
            uint4 ph, pl;
            ph.x = hs[0] | (hs[1] << 16); ph.y = hs[2] | (hs[3] << 16);
            ph.z = hs[4] | (hs[5] << 16); ph.w = hs[6] | (hs[7] << 16);
            pl.x = ls[0] | (ls[1] << 16); pl.y = ls[2] | (ls[3] << 16);
            pl.z = ls[4] | (ls[5] << 16); pl.w = ls[6] | (ls[7] << 16);
            *(uint4*)(g_xh + i) = ph;
            *(uint4*)(g_xl + i) = pl;
        }
        for (int i = tid; i < BC * JC; i += NTHR) {
            int b = i >> 4, j = i & 15;
            int gi = (b0 + b) * HH + j0 + j;
            g_hsh[0][gi] = 0;
            g_hsl[0][gi] = 0;
        }
        if (tid == 0) {
            *((volatile unsigned*)&g_flags[gb * 2 + 0][gj]) = 0u;
            *((volatile unsigned*)&g_flags[gb * 2 + 1][gj]) = 0u;
        }
    }

    // init barrier (global, count-based, self-cleaning)
    __syncthreads();
    if (tid == 0) {
        __threadfence();
        if (atomicAdd(&g_count, 1u) == NCTA - 1u) {
            g_count = 0;
            __threadfence();
            *((volatile unsigned*)&g_phase) = base + 1u;
        }
        while ((unsigned)(*((volatile unsigned*)&g_phase) - base) < 1u) {
            __nanosleep(32);
        }
        __threadfence();
    }
    __syncthreads();

    // mma warp roles: w<12 -> (ntile = w>>2, ksl = w&3)
    const int w     = tid >> 5;
    const int lane  = tid & 31;
    const int ntile = w >> 2;
    const int ksl   = w & 3;

    wmma::fragment<wmma::matrix_a, 16, 16, 16, __nv_bfloat16, wmma::row_major> fa_h, fa_l;
    wmma::fragment<wmma::matrix_b, 16, 16, 16, __nv_bfloat16, wmma::col_major> fb_h, fb_l;
    wmma::fragment<wmma::accumulator, 16, 16, 16, float> facc;

    // h-staging: 32 threads/row, 16 u16 per plane each
    const int hrow = tid >> 5;            // 0..15
    const int hseg = (tid & 31) * 16;     // col base (u16)

    // x-staging by upper thread half: 16 threads/row, 16 u16 per plane
    const int tid2 = tid & 255;
    const int xrow = tid2 >> 4;           // 0..15
    const int xseg = (tid2 & 15) * 16;

    // gate mapping (threads 0-255): one (row, j) element
    const int jj = tid & 15;
    const int bb = (tid >> 4) & 15;       // row within half
    const float bias_r  = B_s[jj];
    const float bias_z  = B_s[16 + jj];
    const float bias_xn = B_s[32 + jj];
    const float bias_hn = B_s[48 + jj];
    const int loc = bb * 16 + jj;
    float hold[2] = {0.0f, 0.0f};

    // stage x(t) of half hx into BU planes (upper 256 threads; also used
    // with full block in the prologue via both halves of threads)
    auto stage_x_half = [&](int t, int hx) {
        const size_t off = ((size_t)(b0 + hx * 16 + xrow) * TT + t) * II + xseg;
        const uint4* sh = (const uint4*)(g_xh + off);
        const uint4* sl = (const uint4*)(g_xl + off);
        uint4* dh = (uint4*)(BUh + xrow * USTRIDE + xseg);
        uint4* dl = (uint4*)(BUl + xrow * USTRIDE + xseg);
        dh[0] = sh[0]; dh[1] = sh[1];
        dl[0] = sl[0]; dl[1] = sl[1];
    };

    // prologue: stage x_A(0) (lower 256 threads cover it fully)
    if (tid < 256) stage_x_half(0, 0);
    __syncthreads();

    for (int t = 0; t < TT; t++) {
        const int rp = t & 1;
        const int wp = rp ^ 1;

        #pragma unroll
        for (int hx = 0; hx < 2; hx++) {
            const int fg = gb * 2 + hx;

            // ---- chunk 0: x projection of this half (BU holds x_hx(t)) ----
            if (w < 12) {
                wmma::fill_fragment(facc, 0.0f);
                const __nv_bfloat16* Ah = (const __nv_bfloat16*)BUh;
                const __nv_bfloat16* Al = (const __nv_bfloat16*)BUl;
                const __nv_bfloat16* Bh = (const __nv_bfloat16*)(Wh + ntile * 16 * WSTRIDE);
                const __nv_bfloat16* Bl = (const __nv_bfloat16*)(Wl + ntile * 16 * WSTRIDE);
                #pragma unroll
                for (int kk = 0; kk < 4; kk++) {
                    const int ks = ksl * 4 + kk;
                    wmma::load_matrix_sync(fa_h, Ah + ks * 16, USTRIDE);
                    wmma::load_matrix_sync(fa_l, Al + ks * 16, USTRIDE);
                    wmma::load_matrix_sync(fb_h, Bh + ks * 16, WSTRIDE);
                    wmma::load_matrix_sync(fb_l, Bl + ks * 16, WSTRIDE);
                    wmma::mma_sync(facc, fa_h, fb_h, facc);
                    wmma::mma_sync(facc, fa_h, fb_l, facc);
                    wmma::mma_sync(facc, fa_l, fb_h, facc);
                }
                if (ntile == 2) {   // n-gate: keep x part separate
                    wmma::store_matrix_sync(Dxn + ksl * 256, facc, 16, wmma::mem_row_major);
                    wmma::fill_fragment(facc, 0.0f);
                }
            }

            // ---- wait: 32 producer flags of this half >= t ----
            if (w == 0) {
                const volatile unsigned* fl = &g_flags[fg][0];
                for (;;) {
                    unsigned v = fl[lane];
                    if (!__any_sync(0xFFFFFFFFu, v < (unsigned)t)) break;
                    __nanosleep(32);
                }
                __threadfence();
            }
            __syncthreads();

            // ---- stage h half: cols 0-255 -> BH1, 256-511 -> BU ----
            {
                const int goff = (b0 + hx * 16 + hrow) * HH + hseg;
                const uint4* sh = (const uint4*)(g_hsh[rp] + goff);
                const uint4* sl = (const uint4*)(g_hsl[rp] + goff);
                uint4 *dh, *dl;
                if (hseg < 256) {
                    dh = (uint4*)(BH1h + hrow * USTRIDE + hseg);
                    dl = (uint4*)(BH1l + hrow * USTRIDE + hseg);
                } else {
                    dh = (uint4*)(BUh + hrow * USTRIDE + (hseg - 256));
                    dl = (uint4*)(BUl + hrow * USTRIDE + (hseg - 256));
                }
                dh[0] = sh[0]; dh[1] = sh[1];
                dl[0] = sl[0]; dl[1] = sl[1];
            }
            __syncthreads();

            // ---- chunks 1+2: h projection (32 k-steps) ----
            if (w < 12) {
                const __nv_bfloat16* Bh = (const __nv_bfloat16*)(Wh + ntile * 16 * WSTRIDE + 256);
                const __nv_bfloat16* Bl = (const __nv_bfloat16*)(Wl + ntile * 16 * WSTRIDE + 256);
                #pragma unroll
                for (int kk = 0; kk < 8; kk++) {
                    const int ks = ksl * 8 + kk;
                    const __nv_bfloat16* Ah;
                    const __nv_bfloat16* Al;
                    int ao;
                    if (ks < 16) {
                        Ah = (const __nv_bfloat16*)BH1h; Al = (const __nv_bfloat16*)BH1l;
                        ao = ks * 16;
                    } else {
                        Ah = (const __nv_bfloat16*)BUh;  Al = (const __nv_bfloat16*)BUl;
                        ao = (ks - 16) * 16;
                    }
                    wmma::load_matrix_sync(fa_h, Ah + ao, USTRIDE);
                    wmma::load_matrix_sync(fa_l, Al + ao, USTRIDE);
                    wmma::load_matrix_sync(fb_h, Bh + ks * 16, WSTRIDE);
                    wmma::load_matrix_sync(fb_l, Bl + ks * 16, WSTRIDE);
                    wmma::mma_sync(facc, fa_h, fb_h, facc);
                    wmma::mma_sync(facc, fa_h, fb_l, facc);
                    wmma::mma_sync(facc, fa_l, fb_h, facc);
                }
                wmma::store_matrix_sync(Dred + (ntile * 4 + ksl) * 256,
                                        facc, 16, wmma::mem_row_major);
            }
            __syncthreads();

            // ---- gates (threads 0-255) || x-stage of other half (256-511) ----
            if (tid < 256) {
                float dr = 0.0f, dz = 0.0f, dn = 0.0f, dxn = 0.0f;
                #pragma unroll
                for (int s = 0; s < 4; s++) {
                    dr  += Dred[(0 * 4 + s) * 256 + loc];
                    dz  += Dred[(1 * 4 + s) * 256 + loc];
                    dn  += Dred[(2 * 4 + s) * 256 + loc];
                    dxn += Dxn[s * 256 + loc];
                }
                float r = sigm(dr + bias_r);
                float z = sigm(dz + bias_z);
                float n = tanhf(dxn + bias_xn + r * (dn + bias_hn));
                float hv = n + z * (hold[hx] - n);
                hold[hx] = hv;
                const int gi = (b0 + hx * 16 + bb) * HH + j0 + jj;
                g_hsh[wp][gi] = bhi(hv);
                g_hsl[wp][gi] = blo(hv);
                if (t == TT - 1) out[gi] = hv;
            } else {
                // stage x of the NEXT mini-step's half: hx==0 -> x_B(t),
                // hx==1 -> x_A(t+1). BU is dead (mma done; synced above).
                const int nhx = hx ^ 1;
                const int nt  = (hx == 0) ? t : t + 1;
                if (nt < TT) stage_x_half(nt, nhx);
            }
            __syncthreads();

            // ---- publish this half: flag = t+1 (others race ahead) ----
            if (tid == 0) {
                __threadfence();
                *((volatile unsigned*)&g_flags[fg][gj]) = (unsigned)(t + 1);
            }
        }
    }
}

extern "C" void kernel_launch(void* const* d_in, const int* in_sizes, int n_in,
                              void* d_out, int out_size) {
    (void)in_sizes; (void)n_in; (void)out_size;
    cudaFuncSetAttribute(gru_persistent_kernel,
                         cudaFuncAttributeMaxDynamicSharedMemorySize, SMEM_BYTES);
    gru_persistent_kernel<<<NCTA, NTHR, SMEM_BYTES>>>(
        (const float*)d_in[0],
        (const float*)d_in[1],
        (const float*)d_in[2],
        (const float*)d_in[3],
        (const float*)d_in[4],
        (float*)d_out);
}